// round 15
// baseline (speedup 1.0000x reference)
#include <cuda_runtime.h>
#include <cuda_bf16.h>
#include <math.h>

// Problem constants
#define BATCH      8
#define NPTS       16384
#define NUM_CLASS  100
#define CONVEX_K   10
#define MSKEL      1000
#define MHALF      500                   // skel points per half
#define HPAIRS     250                   // packed pairs per half
#define NGROUP     800                   // BATCH * NUM_CLASS

#define NTH        128
#define TILE_PTS   256
#define PT_PAIRS   128                   // point pairs per tile
#define NTILES     512                   // 131072 pts / 256; 64 tiles per batch
#define NBLKS      1024                  // NTILES * 2 halves
#define TOTAL_PTS  (BATCH * NPTS)        // 131072
#define NKEY       (BATCH * MSKEL)       // 8000

#define FLTMAX_BITS 0x7F7FFFFFu
#define BIGF 3.0e38f

// ---------------- device scratch (static, no allocation) -------------------
// g_skel_min keys: key = FLTMAX_BITS - float_bits(d2); min d2 == max key.
// Identity 0 (BSS zero-init); last block resets to 0 each replay.
__device__ unsigned int g_skel_min[NKEY];
__device__ float        g_ptd2[NTILES * 2 * TILE_PTS]; // [tile][half][256]
__device__ double       g_pt_partial[NTILES];          // per-tile point-dir sum
__device__ float        g_group_convex[NGROUP];
__device__ unsigned int g_tile_ticket[NTILES];         // zero-init, self-reset
__device__ unsigned int g_ticket;                      // zero-init, self-reset

// ---------------- packed f32x2 helpers (FFMA2 path, sm_103a) ---------------
typedef unsigned long long ull;

__device__ __forceinline__ ull pk2(float lo, float hi) {
    ull r; asm("mov.b64 %0, {%1,%2};" : "=l"(r) : "f"(lo), "f"(hi)); return r;
}
__device__ __forceinline__ void up2(ull v, float& lo, float& hi) {
    asm("mov.b64 {%0,%1}, %2;" : "=f"(lo), "=f"(hi) : "l"(v));
}
__device__ __forceinline__ ull fma2(ull a, ull b, ull c) {
    ull d; asm("fma.rn.f32x2 %0, %1, %2, %3;" : "=l"(d) : "l"(a), "l"(b), "l"(c));
    return d;
}

// ============================================================================
// Single fused kernel. grid = 1024 = (tile, skel-half), 128 threads.
//  - convex loss: blocks 0..799 (lanes 0..9 of warp 0)
//  - pass A: 2 pts/thread vs packed m-pairs -> g_ptd2; per-tile 2nd-arriving
//    half-block combines both halves -> g_pt_partial[tile] (cheap early fence)
//  - pass B: 4 owned m (dup in regs) vs 128 packed point-pairs -> atomicMax
//  - last-arriving block: MLP-unrolled final reduction -> out[0]; resets all
//    scratch for graph replay. All sums fixed-order => deterministic.
// ============================================================================
__global__ void __launch_bounds__(NTH)
fused_kernel(const float* __restrict__ xyz, const float* __restrict__ skel,
             const int* __restrict__ labels, float* __restrict__ out)
{
    __shared__ ulonglong2 s_skA[HPAIRS];   // (-2sx pair, -2sy pair)
    __shared__ ulonglong2 s_skB[HPAIRS];   // (-2sz pair,  ss  pair)
    __shared__ ulonglong2 s_ptA[PT_PAIRS]; // ((x0,x1), (y0,y1)) point pairs
    __shared__ ulonglong2 s_ptB[PT_PAIRS]; // ((z0,z1), (pp0,pp1))
    __shared__ double     s_warp[NTH / 32];
    __shared__ bool       s_combine, s_last;

    const int bid  = blockIdx.x;
    const int tile = bid >> 1;
    const int half = bid & 1;
    const int tid  = threadIdx.x;
    const int lane = tid & 31;
    const int b    = tile >> 6;            // batch (64 tiles per batch)

    // ---------------- this thread's TWO points (load first: deep MLP) ------
    const size_t pbase = (size_t)tile * TILE_PTS;
    const size_t pidx0 = (pbase + tid) * 6;
    const size_t pidx1 = (pbase + tid + NTH) * 6;
    const float x0 = xyz[pidx0 + 0], y0 = xyz[pidx0 + 1], z0 = xyz[pidx0 + 2];
    const float x1 = xyz[pidx1 + 0], y1 = xyz[pidx1 + 1], z1 = xyz[pidx1 + 2];

    // -------- convex-hull loss: one group per block (bid < 800) ------------
    if (bid < NGROUP && tid < 16) {
        float contrib = 0.0f;
        const int gb = bid / NUM_CLASS;
        const int gc = bid % NUM_CLASS;
        const float* p  = skel   + (size_t)(gb * MSKEL + gc * CONVEX_K) * 3;
        const int*   lb = labels + (gb * MSKEL + gc * CONVEX_K);
        if (tid < CONVEX_K) {
            const float xi = p[3 * tid + 0];
            const float yi = p[3 * tid + 1];
            const float zi = p[3 * tid + 2];
            float md = BIGF;
            #pragma unroll
            for (int j = 0; j < CONVEX_K; ++j) {
                if (lb[j] == 1) {
                    float dx = xi - p[3 * j + 0];
                    float dy = yi - p[3 * j + 1];
                    float dz = zi - p[3 * j + 2];
                    md = fminf(md, fmaf(dx, dx, fmaf(dy, dy, dz * dz)));
                }
            }
            md = fminf(md, 100000.0f);
            contrib = (lb[tid] != 1) ? md : 0.0f;
        }
        #pragma unroll
        for (int off = 8; off > 0; off >>= 1)
            contrib += __shfl_down_sync(0xffffu, contrib, off);
        if (tid == 0) g_group_convex[bid] = contrib;
    }

    // ---------------- skel half -> smem (folded -2 / ss) --------------------
    {
        const float* sb = skel + ((size_t)b * MSKEL + half * MHALF) * 3;
        for (int i = tid; i < HPAIRS; i += NTH) {
            float ax = sb[6 * i + 0], ay = sb[6 * i + 1], az = sb[6 * i + 2];
            float cx = sb[6 * i + 3], cy = sb[6 * i + 4], cz = sb[6 * i + 5];
            float ssa = fmaf(ax, ax, fmaf(ay, ay, az * az));
            float ssc = fmaf(cx, cx, fmaf(cy, cy, cz * cz));
            s_skA[i] = make_ulonglong2(pk2(-2.f * ax, -2.f * cx),
                                       pk2(-2.f * ay, -2.f * cy));
            s_skB[i] = make_ulonglong2(pk2(-2.f * az, -2.f * cz),
                                       pk2(ssa, ssc));
        }
    }

    // -------- points -> smem as PACKED PAIRS (pair i = points i, i+128) ----
    const float pp0 = fmaf(x0, x0, fmaf(y0, y0, z0 * z0));
    const float pp1 = fmaf(x1, x1, fmaf(y1, y1, z1 * z1));
    s_ptA[tid] = make_ulonglong2(pk2(x0, x1), pk2(y0, y1));
    s_ptB[tid] = make_ulonglong2(pk2(z0, z1), pk2(pp0, pp1));
    __syncthreads();

    // -------- pass B setup: 4 owned m, coords duplicated in registers ------
    ull   mx[4], my[4], mz[4];
    float ms[4], bmA[4], bmB[4];
    {
        #pragma unroll
        for (int k = 0; k < 2; ++k) {
            int pr = 2 * tid + k; if (pr > HPAIRS - 1) pr = HPAIRS - 1;
            ulonglong2 A  = s_skA[pr];
            ulonglong2 Bq = s_skB[pr];
            float va, vb;
            up2(A.x, va, vb);  mx[2 * k] = pk2(va, va);  mx[2 * k + 1] = pk2(vb, vb);
            up2(A.y, va, vb);  my[2 * k] = pk2(va, va);  my[2 * k + 1] = pk2(vb, vb);
            up2(Bq.x, va, vb); mz[2 * k] = pk2(va, va);  mz[2 * k + 1] = pk2(vb, vb);
            up2(Bq.y, ms[2 * k], ms[2 * k + 1]);
            bmA[2 * k] = BIGF; bmA[2 * k + 1] = BIGF;
            bmB[2 * k] = BIGF; bmB[2 * k + 1] = BIGF;
        }
    }

    // ---------------- pass A: 2 points vs the 500 skel in this half --------
    float d2_0, d2_1;
    {
        const ull pxx0 = pk2(x0, x0), pyy0 = pk2(y0, y0), pzz0 = pk2(z0, z0);
        const ull pxx1 = pk2(x1, x1), pyy1 = pk2(y1, y1), pzz1 = pk2(z1, z1);
        float n0a = BIGF, n0b = BIGF, n1a = BIGF, n1b = BIGF;
        float n0c = BIGF, n0d = BIGF, n1c = BIGF, n1d = BIGF;
        #pragma unroll 10
        for (int i = 0; i < HPAIRS; i += 2) {
            const ulonglong2 A0 = s_skA[i],     B0 = s_skB[i];
            const ulonglong2 A1 = s_skA[i + 1], B1 = s_skB[i + 1];
            float ea, eb;
            ull e00 = fma2(pxx0, A0.x, fma2(pyy0, A0.y, fma2(pzz0, B0.x, B0.y)));
            ull e10 = fma2(pxx1, A0.x, fma2(pyy1, A0.y, fma2(pzz1, B0.x, B0.y)));
            ull e01 = fma2(pxx0, A1.x, fma2(pyy0, A1.y, fma2(pzz0, B1.x, B1.y)));
            ull e11 = fma2(pxx1, A1.x, fma2(pyy1, A1.y, fma2(pzz1, B1.x, B1.y)));
            up2(e00, ea, eb); n0a = fminf(n0a, ea); n0b = fminf(n0b, eb);
            up2(e10, ea, eb); n1a = fminf(n1a, ea); n1b = fminf(n1b, eb);
            up2(e01, ea, eb); n0c = fminf(n0c, ea); n0d = fminf(n0d, eb);
            up2(e11, ea, eb); n1c = fminf(n1c, ea); n1d = fminf(n1d, eb);
        }
        float mn0 = fminf(fminf(n0a, n0b), fminf(n0c, n0d));
        float mn1 = fminf(fminf(n1a, n1b), fminf(n1c, n1d));
        d2_0 = fmaxf(mn0 + pp0, 1e-12f);
        d2_1 = fmaxf(mn1 + pp1, 1e-12f);
        float* dst = g_ptd2 + ((size_t)tile * 2 + half) * TILE_PTS;
        dst[tid]       = d2_0;
        dst[tid + NTH] = d2_1;
    }

    // ---- tile ticket NOW (only 2 STGs outstanding -> cheap fence) ----------
    if (tid == 0) {
        __threadfence();
        unsigned int t = atomicAdd(&g_tile_ticket[tile], 1u);
        s_combine = (t == 1u);
    }
    __syncthreads();

    if (s_combine) {       // 2nd-arriving half: combine point-dir for tile
        __threadfence();   // acquire other half's g_ptd2 writes
        const float* oth = g_ptd2 + ((size_t)tile * 2 + (half ^ 1)) * TILE_PTS;
        float o0 = oth[tid], o1 = oth[tid + NTH];
        double t = (double)sqrtf(fminf(d2_0, o0))
                 + (double)sqrtf(fminf(d2_1, o1));
        #pragma unroll
        for (int off = 16; off > 0; off >>= 1)
            t += __shfl_down_sync(0xffffffffu, t, off);
        if (lane == 0) s_warp[tid >> 5] = t;
        __syncthreads();
        if (tid == 0) {
            g_pt_partial[tile] = s_warp[0] + s_warp[1] + s_warp[2] + s_warp[3];
            g_tile_ticket[tile] = 0u;      // reset for next replay
        }
    }

    // ------- pass B: 4 owned m vs 128 point-pairs (8 distances / 2 LDS) ----
    {
        #pragma unroll 4
        for (int i = 0; i < PT_PAIRS; ++i) {
            const ulonglong2 PA = s_ptA[i];   // (x0,x1),(y0,y1)
            const ulonglong2 PB = s_ptB[i];   // (z0,z1),(pp0,pp1)
            #pragma unroll
            for (int k = 0; k < 4; ++k) {
                ull e = fma2(mx[k], PA.x,
                         fma2(my[k], PA.y,
                          fma2(mz[k], PB.x, PB.y)));   // (pp - 2 p.s) x2 pts
                float ea, eb; up2(e, ea, eb);
                bmA[k] = fminf(bmA[k], ea);
                bmB[k] = fminf(bmB[k], eb);
            }
        }
        if (tid < 125) {
            const int mbase = b * MSKEL + half * MHALF + 4 * tid;
            #pragma unroll
            for (int k = 0; k < 4; ++k) {
                float d2 = fmaxf(fminf(bmA[k], bmB[k]) + ms[k], 0.0f);
                atomicMax(&g_skel_min[mbase + k],
                          FLTMAX_BITS - __float_as_uint(d2));
            }
        }
    }

    // ---------------- global ticket: last block finalizes ------------------
    __syncthreads();
    if (tid == 0) {
        __threadfence();                   // release atomics + g_pt_partial
        unsigned int t = atomicAdd(&g_ticket, 1u);
        s_last = (t == NBLKS - 1);
    }
    __syncthreads();

    if (s_last) {
        __threadfence();                   // acquire all blocks' writes
        double v = 0.0;
        // skel-direction: 8000 keys, MLP-8 unroll (62 full rounds + tail)
        #pragma unroll 8
        for (int idx = tid; idx < NKEY; idx += NTH) {
            unsigned int key = g_skel_min[idx];
            float d2 = __uint_as_float(FLTMAX_BITS - key);
            v += (double)sqrtf(fmaxf(d2, 1e-12f));
            g_skel_min[idx] = 0u;
        }
        // point-direction tile partials (512 doubles, 4 per thread)
        #pragma unroll 4
        for (int i = tid; i < NTILES; i += NTH) v += g_pt_partial[i];
        double cv = 0.0;
        #pragma unroll 7
        for (int i = tid; i < NGROUP; i += NTH) cv += (double)g_group_convex[i];

        double total = cv * (1.0 / (double)NGROUP) + v * (0.1 / (double)BATCH);
        #pragma unroll
        for (int off = 16; off > 0; off >>= 1)
            total += __shfl_down_sync(0xffffffffu, total, off);
        if (lane == 0) s_warp[tid >> 5] = total;
        __syncthreads();
        if (tid == 0) {
            out[0] = (float)(s_warp[0] + s_warp[1] + s_warp[2] + s_warp[3]);
            g_ticket = 0u;                 // reset for next graph replay
        }
    }
}

// ============================================================================
extern "C" void kernel_launch(void* const* d_in, const int* in_sizes, int n_in,
                              void* d_out, int out_size)
{
    const float* xyz    = (const float*)d_in[0];   // [8,16384,6]
    const float* skel   = (const float*)d_in[1];   // [8,1000,3]
    // d_in[2] = weights (unused by reference)
    const int*   labels = (const int*)d_in[3];     // [8,100,10]
    float* out = (float*)d_out;

    fused_kernel<<<NBLKS, NTH>>>(xyz, skel, labels, out);
}

// round 16
// speedup vs baseline: 1.3396x; 1.3396x over previous
#include <cuda_runtime.h>
#include <cuda_bf16.h>
#include <math.h>

// Problem constants
#define BATCH      8
#define NPTS       16384
#define NUM_CLASS  100
#define CONVEX_K   10
#define MSKEL      1000
#define MHALF      500                   // skel points per half
#define HPAIRS     250                   // packed pairs per half
#define NGROUP     800                   // BATCH * NUM_CLASS

#define NTH        128
#define TILE_PTS   256
#define PT_PAIRS   128                   // point pairs per tile
#define NTILES     512                   // 131072 pts / 256; 64 tiles per batch
#define NBLKS      1024                  // NTILES * 2 halves
#define TOTAL_PTS  (BATCH * NPTS)        // 131072

#define PT_BLOCKS  128                   // point-reduce blocks (float4)
#define SK_BLOCKS  8                     // skel-key reduce blocks
#define RED_BLOCKS (PT_BLOCKS + SK_BLOCKS)

#define FLTMAX_BITS 0x7F7FFFFFu
#define BIGF 3.0e38f

// ---------------- device scratch (static, no allocation) -------------------
// g_skel_min keys: key = FLTMAX_BITS - float_bits(d2); min d2 == max key.
// Identity 0 (BSS zero-init); reduce kernel resets to 0 each replay.
__device__ unsigned int g_skel_min[BATCH * MSKEL];
__device__ float        g_ptd2[2 * TOTAL_PTS];   // per (half, point) min d2
__device__ float        g_group_convex[NGROUP];
__device__ double       g_partial[RED_BLOCKS];
__device__ unsigned int g_ticket;                // zero-init; reset by last block

// ---------------- packed f32x2 helpers (FFMA2 path, sm_103a) ---------------
typedef unsigned long long ull;

__device__ __forceinline__ ull pk2(float lo, float hi) {
    ull r; asm("mov.b64 %0, {%1,%2};" : "=l"(r) : "f"(lo), "f"(hi)); return r;
}
__device__ __forceinline__ void up2(ull v, float& lo, float& hi) {
    asm("mov.b64 {%0,%1}, %2;" : "=f"(lo), "=f"(hi) : "l"(v));
}
__device__ __forceinline__ ull fma2(ull a, ull b, ull c) {
    ull d; asm("fma.rn.f32x2 %0, %1, %2, %3;" : "=l"(d) : "l"(a), "l"(b), "l"(c));
    return d;
}

// ============================================================================
// Kernel 1: grid = 1024 = (tile, skel-half). 256-pt tile vs 500 skel points.
// Pass A: 2 points/thread (duplicated in registers) vs packed m-pairs in smem.
// Pass B: thread owns 4 m (coords duplicated in registers at setup) and
//         iterates 128 POINT-PAIRS packed in smem (no duplication).
// Convex loss: blocks 0..799, lanes 0..9 of warp 0.
// Ends with griddepcontrol.launch_dependents (PDL release to reduce_kernel).
// ============================================================================
__global__ void __launch_bounds__(NTH)
fused_kernel(const float* __restrict__ xyz, const float* __restrict__ skel,
             const int* __restrict__ labels)
{
    __shared__ ulonglong2 s_skA[HPAIRS];   // (-2sx pair, -2sy pair)
    __shared__ ulonglong2 s_skB[HPAIRS];   // (-2sz pair,  ss  pair)
    __shared__ ulonglong2 s_ptA[PT_PAIRS]; // ((x0,x1), (y0,y1)) point pairs
    __shared__ ulonglong2 s_ptB[PT_PAIRS]; // ((z0,z1), (pp0,pp1))

    const int bid  = blockIdx.x;
    const int tile = bid >> 1;
    const int half = bid & 1;
    const int tid  = threadIdx.x;
    const int b    = tile >> 6;            // batch (64 tiles per batch)

    // ---------------- this thread's TWO points (load first: deep MLP) ------
    const size_t pbase = (size_t)tile * TILE_PTS;
    const size_t pidx0 = (pbase + tid) * 6;
    const size_t pidx1 = (pbase + tid + NTH) * 6;
    const float x0 = xyz[pidx0 + 0], y0 = xyz[pidx0 + 1], z0 = xyz[pidx0 + 2];
    const float x1 = xyz[pidx1 + 0], y1 = xyz[pidx1 + 1], z1 = xyz[pidx1 + 2];

    // -------- convex-hull loss: one group per block (bid < 800) ------------
    if (bid < NGROUP && tid < 16) {
        float contrib = 0.0f;
        const int gb = bid / NUM_CLASS;
        const int gc = bid % NUM_CLASS;
        const float* p  = skel   + (size_t)(gb * MSKEL + gc * CONVEX_K) * 3;
        const int*   lb = labels + (gb * MSKEL + gc * CONVEX_K);
        if (tid < CONVEX_K) {
            const float xi = p[3 * tid + 0];
            const float yi = p[3 * tid + 1];
            const float zi = p[3 * tid + 2];
            float md = BIGF;
            #pragma unroll
            for (int j = 0; j < CONVEX_K; ++j) {
                if (lb[j] == 1) {
                    float dx = xi - p[3 * j + 0];
                    float dy = yi - p[3 * j + 1];
                    float dz = zi - p[3 * j + 2];
                    md = fminf(md, fmaf(dx, dx, fmaf(dy, dy, dz * dz)));
                }
            }
            md = fminf(md, 100000.0f);
            contrib = (lb[tid] != 1) ? md : 0.0f;
        }
        #pragma unroll
        for (int off = 8; off > 0; off >>= 1)
            contrib += __shfl_down_sync(0xffffu, contrib, off);
        if (tid == 0) g_group_convex[bid] = contrib;
    }

    // ---------------- skel half -> smem (folded -2 / ss) --------------------
    {
        const float* sb = skel + ((size_t)b * MSKEL + half * MHALF) * 3;
        for (int i = tid; i < HPAIRS; i += NTH) {
            float ax = sb[6 * i + 0], ay = sb[6 * i + 1], az = sb[6 * i + 2];
            float cx = sb[6 * i + 3], cy = sb[6 * i + 4], cz = sb[6 * i + 5];
            float ssa = fmaf(ax, ax, fmaf(ay, ay, az * az));
            float ssc = fmaf(cx, cx, fmaf(cy, cy, cz * cz));
            s_skA[i] = make_ulonglong2(pk2(-2.f * ax, -2.f * cx),
                                       pk2(-2.f * ay, -2.f * cy));
            s_skB[i] = make_ulonglong2(pk2(-2.f * az, -2.f * cz),
                                       pk2(ssa, ssc));
        }
    }

    // -------- points -> smem as PACKED PAIRS (pair i = points i, i+128) ----
    const float pp0 = fmaf(x0, x0, fmaf(y0, y0, z0 * z0));
    const float pp1 = fmaf(x1, x1, fmaf(y1, y1, z1 * z1));
    s_ptA[tid] = make_ulonglong2(pk2(x0, x1), pk2(y0, y1));
    s_ptB[tid] = make_ulonglong2(pk2(z0, z1), pk2(pp0, pp1));
    __syncthreads();

    // -------- pass B setup: 4 owned m, coords duplicated in registers ------
    ull   mx[4], my[4], mz[4];
    float ms[4], bmA[4], bmB[4];
    {
        #pragma unroll
        for (int k = 0; k < 2; ++k) {
            int pr = 2 * tid + k; if (pr > HPAIRS - 1) pr = HPAIRS - 1;
            ulonglong2 A  = s_skA[pr];
            ulonglong2 Bq = s_skB[pr];
            float va, vb;
            up2(A.x, va, vb);  mx[2 * k] = pk2(va, va);  mx[2 * k + 1] = pk2(vb, vb);
            up2(A.y, va, vb);  my[2 * k] = pk2(va, va);  my[2 * k + 1] = pk2(vb, vb);
            up2(Bq.x, va, vb); mz[2 * k] = pk2(va, va);  mz[2 * k + 1] = pk2(vb, vb);
            up2(Bq.y, ms[2 * k], ms[2 * k + 1]);
            bmA[2 * k] = BIGF; bmA[2 * k + 1] = BIGF;
            bmB[2 * k] = BIGF; bmB[2 * k + 1] = BIGF;
        }
    }

    // ---------------- pass A: 2 points vs the 500 skel in this half --------
    {
        const ull pxx0 = pk2(x0, x0), pyy0 = pk2(y0, y0), pzz0 = pk2(z0, z0);
        const ull pxx1 = pk2(x1, x1), pyy1 = pk2(y1, y1), pzz1 = pk2(z1, z1);
        float n0a = BIGF, n0b = BIGF, n1a = BIGF, n1b = BIGF;
        float n0c = BIGF, n0d = BIGF, n1c = BIGF, n1d = BIGF;
        #pragma unroll 10
        for (int i = 0; i < HPAIRS; i += 2) {
            const ulonglong2 A0 = s_skA[i],     B0 = s_skB[i];
            const ulonglong2 A1 = s_skA[i + 1], B1 = s_skB[i + 1];
            float ea, eb;
            ull e00 = fma2(pxx0, A0.x, fma2(pyy0, A0.y, fma2(pzz0, B0.x, B0.y)));
            ull e10 = fma2(pxx1, A0.x, fma2(pyy1, A0.y, fma2(pzz1, B0.x, B0.y)));
            ull e01 = fma2(pxx0, A1.x, fma2(pyy0, A1.y, fma2(pzz0, B1.x, B1.y)));
            ull e11 = fma2(pxx1, A1.x, fma2(pyy1, A1.y, fma2(pzz1, B1.x, B1.y)));
            up2(e00, ea, eb); n0a = fminf(n0a, ea); n0b = fminf(n0b, eb);
            up2(e10, ea, eb); n1a = fminf(n1a, ea); n1b = fminf(n1b, eb);
            up2(e01, ea, eb); n0c = fminf(n0c, ea); n0d = fminf(n0d, eb);
            up2(e11, ea, eb); n1c = fminf(n1c, ea); n1d = fminf(n1d, eb);
        }
        float mn0 = fminf(fminf(n0a, n0b), fminf(n0c, n0d));
        float mn1 = fminf(fminf(n1a, n1b), fminf(n1c, n1d));
        g_ptd2[(size_t)half * TOTAL_PTS + pbase + tid]
            = fmaxf(mn0 + pp0, 1e-12f);
        g_ptd2[(size_t)half * TOTAL_PTS + pbase + tid + NTH]
            = fmaxf(mn1 + pp1, 1e-12f);
    }

    // ------- pass B: 4 owned m vs 128 point-pairs (8 distances / 2 LDS) ----
    {
        #pragma unroll 4
        for (int i = 0; i < PT_PAIRS; ++i) {
            const ulonglong2 PA = s_ptA[i];   // (x0,x1),(y0,y1)
            const ulonglong2 PB = s_ptB[i];   // (z0,z1),(pp0,pp1)
            #pragma unroll
            for (int k = 0; k < 4; ++k) {
                ull e = fma2(mx[k], PA.x,
                         fma2(my[k], PA.y,
                          fma2(mz[k], PB.x, PB.y)));   // (pp - 2 p.s) x2 pts
                float ea, eb; up2(e, ea, eb);
                bmA[k] = fminf(bmA[k], ea);
                bmB[k] = fminf(bmB[k], eb);
            }
        }
        if (tid < 125) {
            const int mbase = b * MSKEL + half * MHALF + 4 * tid;
            #pragma unroll
            for (int k = 0; k < 4; ++k) {
                float d2 = fmaxf(fminf(bmA[k], bmB[k]) + ms[k], 0.0f);
                atomicMax(&g_skel_min[mbase + k],
                          FLTMAX_BITS - __float_as_uint(d2));
            }
        }
    }

    // PDL: signal dependent grid; carries memory-visibility of all writes.
    asm volatile("griddepcontrol.launch_dependents;" ::: "memory");
}

// ============================================================================
// Kernel 2 (PDL dependent): merged reductions + last-block combine.
// Launched with programmatic stream serialization: blocks come resident
// during the fused kernel's tail, then gate on griddepcontrol.wait.
// ============================================================================
__global__ void __launch_bounds__(256)
reduce_kernel(float* __restrict__ out)
{
    __shared__ double s_red[256];
    __shared__ bool   s_last;
    const int bid = blockIdx.x;
    const int tid = threadIdx.x;

    // Gate: wait until fused grid signalled (all its writes visible after).
    asm volatile("griddepcontrol.wait;" ::: "memory");

    double v = 0.0;
    if (bid < PT_BLOCKS) {
        const float4* p0 = reinterpret_cast<const float4*>(g_ptd2);
        const float4* p1 = reinterpret_cast<const float4*>(g_ptd2 + TOTAL_PTS);
        const int g = bid * 256 + tid;              // 0..32767
        float4 a = p0[g], c = p1[g];
        v  = (double)sqrtf(fminf(a.x, c.x));
        v += (double)sqrtf(fminf(a.y, c.y));
        v += (double)sqrtf(fminf(a.z, c.z));
        v += (double)sqrtf(fminf(a.w, c.w));
    } else {
        const int i0 = (bid - PT_BLOCKS) * 256 + tid;   // 0..2047
        #pragma unroll
        for (int k = 0; k < 4; ++k) {
            const int idx = i0 + k * 2048;              // covers 8192 >= 8000
            if (idx < BATCH * MSKEL) {
                unsigned int key = g_skel_min[idx];
                float d2 = __uint_as_float(FLTMAX_BITS - key);
                v += (double)sqrtf(fmaxf(d2, 1e-12f));
                g_skel_min[idx] = 0u;       // reset identity for next replay
            }
        }
    }

    s_red[tid] = v;
    __syncthreads();
    for (int st = 128; st > 0; st >>= 1) {
        if (tid < st) s_red[tid] += s_red[tid + st];
        __syncthreads();
    }
    if (tid == 0) {
        g_partial[bid] = s_red[0];
        __threadfence();
        unsigned int t = atomicAdd(&g_ticket, 1u);
        s_last = (t == RED_BLOCKS - 1);
    }
    __syncthreads();

    if (s_last) {
        __threadfence();
        double cd = 0.0;
        for (int i = tid; i < RED_BLOCKS; i += 256) cd += g_partial[i];
        double cv = 0.0;
        for (int i = tid; i < NGROUP; i += 256) cv += (double)g_group_convex[i];
        s_red[tid] = cv * (1.0 / (double)NGROUP) + cd * (0.1 / (double)BATCH);
        __syncthreads();
        for (int st = 128; st > 0; st >>= 1) {
            if (tid < st) s_red[tid] += s_red[tid + st];
            __syncthreads();
        }
        if (tid == 0) {
            out[0] = (float)s_red[0];
            g_ticket = 0;                 // reset for next graph replay
        }
    }
}

// ============================================================================
extern "C" void kernel_launch(void* const* d_in, const int* in_sizes, int n_in,
                              void* d_out, int out_size)
{
    const float* xyz    = (const float*)d_in[0];   // [8,16384,6]
    const float* skel   = (const float*)d_in[1];   // [8,1000,3]
    // d_in[2] = weights (unused by reference)
    const int*   labels = (const int*)d_in[3];     // [8,100,10]
    float* out = (float*)d_out;

    fused_kernel<<<NBLKS, NTH>>>(xyz, skel, labels);

    // Dependent launch with programmatic stream serialization (PDL):
    // reduce_kernel's blocks launch under the fused kernel's tail and gate
    // on griddepcontrol.wait inside the kernel.
    cudaLaunchConfig_t cfg = {};
    cfg.gridDim  = dim3(RED_BLOCKS);
    cfg.blockDim = dim3(256);
    cfg.dynamicSmemBytes = 0;
    cfg.stream = 0;
    cudaLaunchAttribute attr[1];
    attr[0].id = cudaLaunchAttributeProgrammaticStreamSerialization;
    attr[0].val.programmaticStreamSerializationAllowed = 1;
    cfg.attrs = attr;
    cfg.numAttrs = 1;
    cudaLaunchKernelEx(&cfg, reduce_kernel, out);
}

// round 17
// speedup vs baseline: 1.3879x; 1.0361x over previous
#include <cuda_runtime.h>
#include <cuda_bf16.h>
#include <math.h>

// Problem constants
#define BATCH      8
#define NPTS       16384
#define NUM_CLASS  100
#define CONVEX_K   10
#define MSKEL      1000
#define MQUAR      250                   // skel points per quarter
#define QPAIRS     125                   // packed pairs per quarter
#define NGROUP     800                   // BATCH * NUM_CLASS

#define NTH        128
#define TILE_PTS   256
#define PT_PAIRS   128                   // point pairs per tile
#define NTILES     512                   // 131072 pts / 256; 64 tiles per batch
#define NBLKS      2048                  // NTILES * 4 quarters
#define TOTAL_PTS  (BATCH * NPTS)        // 131072

#define PT_BLOCKS  128                   // point-reduce blocks (float4)
#define SK_BLOCKS  8                     // skel-key reduce blocks
#define RED_BLOCKS (PT_BLOCKS + SK_BLOCKS)

#define FLTMAX_BITS 0x7F7FFFFFu
#define BIGF 3.0e38f

// ---------------- device scratch (static, no allocation) -------------------
// g_skel_min keys: key = FLTMAX_BITS - float_bits(d2); min d2 == max key.
// Identity 0 (BSS zero-init); reduce kernel resets to 0 each replay.
__device__ unsigned int g_skel_min[BATCH * MSKEL];
__device__ float        g_ptd2[4 * TOTAL_PTS];   // [quarter][point] min d2
__device__ float        g_group_convex[NGROUP];
__device__ double       g_partial[RED_BLOCKS];
__device__ unsigned int g_ticket;                // zero-init; reset by last block

// ---------------- packed f32x2 helpers (FFMA2 path, sm_103a) ---------------
typedef unsigned long long ull;

__device__ __forceinline__ ull pk2(float lo, float hi) {
    ull r; asm("mov.b64 %0, {%1,%2};" : "=l"(r) : "f"(lo), "f"(hi)); return r;
}
__device__ __forceinline__ void up2(ull v, float& lo, float& hi) {
    asm("mov.b64 {%0,%1}, %2;" : "=f"(lo), "=f"(hi) : "l"(v));
}
__device__ __forceinline__ ull fma2(ull a, ull b, ull c) {
    ull d; asm("fma.rn.f32x2 %0, %1, %2, %3;" : "=l"(d) : "l"(a), "l"(b), "l"(c));
    return d;
}

// ============================================================================
// Kernel 1: grid = 2048 = (tile, skel-quarter). 256-pt tile vs 250 skel pts.
// Pass A: 2 points/thread (dup in regs) vs 125 packed m-pairs in smem.
// Pass B: thread owns 1 m-pair (2 m, dup in regs), iterates 128 point-pairs.
// Convex loss: blocks 0..799, lanes 0..9 of warp 0.
// Ends with griddepcontrol.launch_dependents (PDL release to reduce_kernel).
// ============================================================================
__global__ void __launch_bounds__(NTH)
fused_kernel(const float* __restrict__ xyz, const float* __restrict__ skel,
             const int* __restrict__ labels)
{
    __shared__ ulonglong2 s_skA[QPAIRS];   // (-2sx pair, -2sy pair)
    __shared__ ulonglong2 s_skB[QPAIRS];   // (-2sz pair,  ss  pair)
    __shared__ ulonglong2 s_ptA[PT_PAIRS]; // ((x0,x1), (y0,y1)) point pairs
    __shared__ ulonglong2 s_ptB[PT_PAIRS]; // ((z0,z1), (pp0,pp1))

    const int bid  = blockIdx.x;
    const int tile = bid >> 2;
    const int quar = bid & 3;
    const int tid  = threadIdx.x;
    const int b    = tile >> 6;            // batch (64 tiles per batch)

    // ---------------- this thread's TWO points (load first: deep MLP) ------
    const size_t pbase = (size_t)tile * TILE_PTS;
    const size_t pidx0 = (pbase + tid) * 6;
    const size_t pidx1 = (pbase + tid + NTH) * 6;
    const float x0 = xyz[pidx0 + 0], y0 = xyz[pidx0 + 1], z0 = xyz[pidx0 + 2];
    const float x1 = xyz[pidx1 + 0], y1 = xyz[pidx1 + 1], z1 = xyz[pidx1 + 2];

    // -------- convex-hull loss: one group per block (bid < 800) ------------
    if (bid < NGROUP && tid < 16) {
        float contrib = 0.0f;
        const int gb = bid / NUM_CLASS;
        const int gc = bid % NUM_CLASS;
        const float* p  = skel   + (size_t)(gb * MSKEL + gc * CONVEX_K) * 3;
        const int*   lb = labels + (gb * MSKEL + gc * CONVEX_K);
        if (tid < CONVEX_K) {
            const float xi = p[3 * tid + 0];
            const float yi = p[3 * tid + 1];
            const float zi = p[3 * tid + 2];
            float md = BIGF;
            #pragma unroll
            for (int j = 0; j < CONVEX_K; ++j) {
                if (lb[j] == 1) {
                    float dx = xi - p[3 * j + 0];
                    float dy = yi - p[3 * j + 1];
                    float dz = zi - p[3 * j + 2];
                    md = fminf(md, fmaf(dx, dx, fmaf(dy, dy, dz * dz)));
                }
            }
            md = fminf(md, 100000.0f);
            contrib = (lb[tid] != 1) ? md : 0.0f;
        }
        #pragma unroll
        for (int off = 8; off > 0; off >>= 1)
            contrib += __shfl_down_sync(0xffffu, contrib, off);
        if (tid == 0) g_group_convex[bid] = contrib;
    }

    // ---------------- skel quarter -> smem (folded -2 / ss) -----------------
    if (tid < QPAIRS) {
        const float* sb = skel + ((size_t)b * MSKEL + quar * MQUAR) * 3;
        const int i = tid;
        float ax = sb[6 * i + 0], ay = sb[6 * i + 1], az = sb[6 * i + 2];
        float cx = sb[6 * i + 3], cy = sb[6 * i + 4], cz = sb[6 * i + 5];
        float ssa = fmaf(ax, ax, fmaf(ay, ay, az * az));
        float ssc = fmaf(cx, cx, fmaf(cy, cy, cz * cz));
        s_skA[i] = make_ulonglong2(pk2(-2.f * ax, -2.f * cx),
                                   pk2(-2.f * ay, -2.f * cy));
        s_skB[i] = make_ulonglong2(pk2(-2.f * az, -2.f * cz),
                                   pk2(ssa, ssc));
    }

    // -------- points -> smem as PACKED PAIRS (pair i = points i, i+128) ----
    const float pp0 = fmaf(x0, x0, fmaf(y0, y0, z0 * z0));
    const float pp1 = fmaf(x1, x1, fmaf(y1, y1, z1 * z1));
    s_ptA[tid] = make_ulonglong2(pk2(x0, x1), pk2(y0, y1));
    s_ptB[tid] = make_ulonglong2(pk2(z0, z1), pk2(pp0, pp1));
    __syncthreads();

    // -------- pass B setup: 1 owned m-pair (2 m), coords dup'd in regs -----
    ull   mx0, my0, mz0, mx1, my1, mz1;
    float ms0, ms1, bmA0, bmB0, bmA1, bmB1;
    {
        int pr = tid; if (pr > QPAIRS - 1) pr = QPAIRS - 1;
        ulonglong2 A  = s_skA[pr];
        ulonglong2 Bq = s_skB[pr];
        float va, vb;
        up2(A.x, va, vb);  mx0 = pk2(va, va);  mx1 = pk2(vb, vb);
        up2(A.y, va, vb);  my0 = pk2(va, va);  my1 = pk2(vb, vb);
        up2(Bq.x, va, vb); mz0 = pk2(va, va);  mz1 = pk2(vb, vb);
        up2(Bq.y, ms0, ms1);
        bmA0 = BIGF; bmB0 = BIGF; bmA1 = BIGF; bmB1 = BIGF;
    }

    // ---------------- pass A: 2 points vs the 250 skel in this quarter -----
    {
        const ull pxx0 = pk2(x0, x0), pyy0 = pk2(y0, y0), pzz0 = pk2(z0, z0);
        const ull pxx1 = pk2(x1, x1), pyy1 = pk2(y1, y1), pzz1 = pk2(z1, z1);
        float n0a = BIGF, n0b = BIGF, n1a = BIGF, n1b = BIGF;
        #pragma unroll 5
        for (int i = 0; i < QPAIRS; ++i) {
            const ulonglong2 A = s_skA[i], Bq = s_skB[i];
            float ea, eb;
            ull e0 = fma2(pxx0, A.x, fma2(pyy0, A.y, fma2(pzz0, Bq.x, Bq.y)));
            ull e1 = fma2(pxx1, A.x, fma2(pyy1, A.y, fma2(pzz1, Bq.x, Bq.y)));
            up2(e0, ea, eb); n0a = fminf(n0a, ea); n0b = fminf(n0b, eb);
            up2(e1, ea, eb); n1a = fminf(n1a, ea); n1b = fminf(n1b, eb);
        }
        float mn0 = fminf(n0a, n0b);
        float mn1 = fminf(n1a, n1b);
        float* dst = g_ptd2 + (size_t)quar * TOTAL_PTS + pbase;
        dst[tid]       = fmaxf(mn0 + pp0, 1e-12f);
        dst[tid + NTH] = fmaxf(mn1 + pp1, 1e-12f);
    }

    // ------- pass B: 2 owned m vs 128 point-pairs --------------------------
    {
        #pragma unroll 4
        for (int i = 0; i < PT_PAIRS; ++i) {
            const ulonglong2 PA = s_ptA[i];   // (x0,x1),(y0,y1)
            const ulonglong2 PB = s_ptB[i];   // (z0,z1),(pp0,pp1)
            float ea, eb;
            ull e0 = fma2(mx0, PA.x, fma2(my0, PA.y, fma2(mz0, PB.x, PB.y)));
            ull e1 = fma2(mx1, PA.x, fma2(my1, PA.y, fma2(mz1, PB.x, PB.y)));
            up2(e0, ea, eb); bmA0 = fminf(bmA0, ea); bmB0 = fminf(bmB0, eb);
            up2(e1, ea, eb); bmA1 = fminf(bmA1, ea); bmB1 = fminf(bmB1, eb);
        }
        if (tid < QPAIRS) {
            const int mbase = b * MSKEL + quar * MQUAR + 2 * tid;
            float d2a = fmaxf(fminf(bmA0, bmB0) + ms0, 0.0f);
            float d2b = fmaxf(fminf(bmA1, bmB1) + ms1, 0.0f);
            atomicMax(&g_skel_min[mbase],     FLTMAX_BITS - __float_as_uint(d2a));
            atomicMax(&g_skel_min[mbase + 1], FLTMAX_BITS - __float_as_uint(d2b));
        }
    }

    // PDL: signal dependent grid; carries memory-visibility of all writes.
    asm volatile("griddepcontrol.launch_dependents;" ::: "memory");
}

// ============================================================================
// Kernel 2 (PDL dependent): merged reductions + last-block combine.
// ============================================================================
__global__ void __launch_bounds__(256)
reduce_kernel(float* __restrict__ out)
{
    __shared__ double s_red[256];
    __shared__ bool   s_last;
    const int bid = blockIdx.x;
    const int tid = threadIdx.x;

    // Gate: wait until fused grid signalled (all its writes visible after).
    asm volatile("griddepcontrol.wait;" ::: "memory");

    double v = 0.0;
    if (bid < PT_BLOCKS) {
        const float4* p0 = reinterpret_cast<const float4*>(g_ptd2);
        const float4* p1 = reinterpret_cast<const float4*>(g_ptd2 + TOTAL_PTS);
        const float4* p2 = reinterpret_cast<const float4*>(g_ptd2 + 2 * (size_t)TOTAL_PTS);
        const float4* p3 = reinterpret_cast<const float4*>(g_ptd2 + 3 * (size_t)TOTAL_PTS);
        const int g = bid * 256 + tid;              // 0..32767
        float4 a = p0[g], c = p1[g], d = p2[g], e = p3[g];
        v  = (double)sqrtf(fminf(fminf(a.x, c.x), fminf(d.x, e.x)));
        v += (double)sqrtf(fminf(fminf(a.y, c.y), fminf(d.y, e.y)));
        v += (double)sqrtf(fminf(fminf(a.z, c.z), fminf(d.z, e.z)));
        v += (double)sqrtf(fminf(fminf(a.w, c.w), fminf(d.w, e.w)));
    } else {
        const int i0 = (bid - PT_BLOCKS) * 256 + tid;   // 0..2047
        #pragma unroll
        for (int k = 0; k < 4; ++k) {
            const int idx = i0 + k * 2048;              // covers 8192 >= 8000
            if (idx < BATCH * MSKEL) {
                unsigned int key = g_skel_min[idx];
                float d2 = __uint_as_float(FLTMAX_BITS - key);
                v += (double)sqrtf(fmaxf(d2, 1e-12f));
                g_skel_min[idx] = 0u;       // reset identity for next replay
            }
        }
    }

    s_red[tid] = v;
    __syncthreads();
    for (int st = 128; st > 0; st >>= 1) {
        if (tid < st) s_red[tid] += s_red[tid + st];
        __syncthreads();
    }
    if (tid == 0) {
        g_partial[bid] = s_red[0];
        __threadfence();
        unsigned int t = atomicAdd(&g_ticket, 1u);
        s_last = (t == RED_BLOCKS - 1);
    }
    __syncthreads();

    if (s_last) {
        __threadfence();
        double cd = 0.0;
        for (int i = tid; i < RED_BLOCKS; i += 256) cd += g_partial[i];
        double cv = 0.0;
        for (int i = tid; i < NGROUP; i += 256) cv += (double)g_group_convex[i];
        s_red[tid] = cv * (1.0 / (double)NGROUP) + cd * (0.1 / (double)BATCH);
        __syncthreads();
        for (int st = 128; st > 0; st >>= 1) {
            if (tid < st) s_red[tid] += s_red[tid + st];
            __syncthreads();
        }
        if (tid == 0) {
            out[0] = (float)s_red[0];
            g_ticket = 0;                 // reset for next graph replay
        }
    }
}

// ============================================================================
extern "C" void kernel_launch(void* const* d_in, const int* in_sizes, int n_in,
                              void* d_out, int out_size)
{
    const float* xyz    = (const float*)d_in[0];   // [8,16384,6]
    const float* skel   = (const float*)d_in[1];   // [8,1000,3]
    // d_in[2] = weights (unused by reference)
    const int*   labels = (const int*)d_in[3];     // [8,100,10]
    float* out = (float*)d_out;

    fused_kernel<<<NBLKS, NTH>>>(xyz, skel, labels);

    // Dependent launch with programmatic stream serialization (PDL).
    cudaLaunchConfig_t cfg = {};
    cfg.gridDim  = dim3(RED_BLOCKS);
    cfg.blockDim = dim3(256);
    cfg.dynamicSmemBytes = 0;
    cfg.stream = 0;
    cudaLaunchAttribute attr[1];
    attr[0].id = cudaLaunchAttributeProgrammaticStreamSerialization;
    attr[0].val.programmaticStreamSerializationAllowed = 1;
    cfg.attrs = attr;
    cfg.numAttrs = 1;
    cudaLaunchKernelEx(&cfg, reduce_kernel, out);
}